// round 1
// baseline (speedup 1.0000x reference)
#include <cuda_runtime.h>

#define N_NODES 100000
#define N_EDGES 1600000
#define IN_DIM  256
#define HID     128
#define OUT_DIM 40

// ---- scratch (static device globals; allocation-free per harness rules) ----
__device__ float g_deg[N_NODES];
__device__ float g_isd[N_NODES];
__device__ float g_coeff[N_EDGES];
__device__ float g_h1[(size_t)N_NODES * HID];    // 51.2 MB
__device__ float g_agg1[(size_t)N_NODES * HID];  // 51.2 MB
__device__ float g_h2[(size_t)N_NODES * OUT_DIM];// 16 MB

// ---------------------------------------------------------------- degree ----
__global__ void k_zero_deg(int n) {
    int i = blockIdx.x * blockDim.x + threadIdx.x;
    if (i < n) g_deg[i] = 0.f;
}

__global__ void k_count(const int* __restrict__ dst, int e) {
    int i = blockIdx.x * blockDim.x + threadIdx.x;
    if (i < e) atomicAdd(&g_deg[dst[i]], 1.0f);
}

__global__ void k_isd(int n) {
    int i = blockIdx.x * blockDim.x + threadIdx.x;
    if (i < n) {
        float d = g_deg[i];
        g_isd[i] = (d > 0.f) ? rsqrtf(d) : 0.f;
    }
}

__global__ void k_coeff(const int* __restrict__ src, const int* __restrict__ dst, int e) {
    int i = blockIdx.x * blockDim.x + threadIdx.x;
    if (i < e) g_coeff[i] = g_isd[src[i]] * g_isd[dst[i]];
}

// ---------------------------------------------------------------- GEMM1 -----
// h1[N,128] = x[N,256] @ W1[256,128].  BM=64, BN=128 (full), BK=32.
// 256 threads: tx=tid&31 covers N in float4 units (TN=4), ty=tid>>5 covers M (TM=8).
// A-frag loads are warp-uniform broadcasts (lanes share ty) -> conflict-free.
__global__ void k_gemm1(const float* __restrict__ x, const float* __restrict__ W, int n) {
    __shared__ float sA[64][32];   // [m][k]
    __shared__ float sB[32][128];  // [k][n]
    int tid = threadIdx.x;
    int tx = tid & 31, ty = tid >> 5;
    int m0 = blockIdx.x * 64;
    float acc[8][4] = {};

    for (int k0 = 0; k0 < IN_DIM; k0 += 32) {
        // A tile: 64x32 = 512 float4
        #pragma unroll
        for (int j = 0; j < 2; j++) {
            int i = tid + j * 256;
            int r = i >> 3, c = (i & 7) * 4;
            int row = m0 + r;
            float4 v = (row < n) ? *(const float4*)&x[(size_t)row * IN_DIM + k0 + c]
                                 : make_float4(0.f, 0.f, 0.f, 0.f);
            *(float4*)&sA[r][c] = v;
        }
        // B tile: 32x128 = 1024 float4
        #pragma unroll
        for (int j = 0; j < 4; j++) {
            int i = tid + j * 256;
            int r = i >> 5, c = (i & 31) * 4;
            *(float4*)&sB[r][c] = *(const float4*)&W[(size_t)(k0 + r) * HID + c];
        }
        __syncthreads();

        #pragma unroll
        for (int k = 0; k < 32; k++) {
            float4 b = *(float4*)&sB[k][tx * 4];
            #pragma unroll
            for (int mm = 0; mm < 8; mm++) {
                float a = sA[ty * 8 + mm][k];  // warp-uniform broadcast
                acc[mm][0] = fmaf(a, b.x, acc[mm][0]);
                acc[mm][1] = fmaf(a, b.y, acc[mm][1]);
                acc[mm][2] = fmaf(a, b.z, acc[mm][2]);
                acc[mm][3] = fmaf(a, b.w, acc[mm][3]);
            }
        }
        __syncthreads();
    }
    #pragma unroll
    for (int mm = 0; mm < 8; mm++) {
        int row = m0 + ty * 8 + mm;
        if (row < n) {
            float4 v = make_float4(acc[mm][0], acc[mm][1], acc[mm][2], acc[mm][3]);
            *(float4*)&g_h1[(size_t)row * HID + tx * 4] = v;
        }
    }
}

// ------------------------------------------------------- layer1 edge agg ----
__global__ void k_prefill1(const float* __restrict__ b1, int n) {
    int i = blockIdx.x * blockDim.x + threadIdx.x;  // over n*32 float4
    if (i < n * 32) {
        int c = i & 31;
        ((float4*)g_agg1)[i] = ((const float4*)b1)[c];
    }
}

// warp per edge: 32 lanes x float4 = 128 floats. Vector global reduction.
__global__ void k_edge1(const int* __restrict__ src, const int* __restrict__ dst, int e) {
    int gid = blockIdx.x * blockDim.x + threadIdx.x;
    int w = gid >> 5;
    int lane = threadIdx.x & 31;
    if (w >= e) return;
    int s = __ldg(&src[w]);
    int d = __ldg(&dst[w]);
    float c = g_coeff[w];
    float4 v = ((const float4*)g_h1)[(size_t)s * 32 + lane];
    v.x *= c; v.y *= c; v.z *= c; v.w *= c;
    float* p = (float*)(((float4*)g_agg1) + ((size_t)d * 32 + lane));
    asm volatile("red.global.add.v4.f32 [%0], {%1,%2,%3,%4};"
                 :: "l"(p), "f"(v.x), "f"(v.y), "f"(v.z), "f"(v.w) : "memory");
}

// ---------------------------------------------------------------- GEMM2 -----
// h2[N,40] = relu(agg1)[N,128] @ W2[128,40].  BM=32, full N=40.
// 256 threads: m=tid&31 (row), g=tid>>5 (0..7), 5 cols each. W loads warp-uniform.
__global__ void k_gemm2(const float* __restrict__ W2, int n) {
    __shared__ float sW[HID * OUT_DIM];  // 20 KB
    __shared__ float sA[32][129];        // 16.5 KB, pad 129 -> conflict-free
    int tid = threadIdx.x;
    int m0 = blockIdx.x * 32;

    for (int i = tid; i < HID * OUT_DIM; i += 256) sW[i] = W2[i];

    // A tile: 32x128 = 1024 float4, relu fused
    #pragma unroll
    for (int j = 0; j < 4; j++) {
        int i = tid + j * 256;
        int r = i >> 5, c = (i & 31) * 4;
        int row = m0 + r;
        float4 v = (row < n) ? *(const float4*)&g_agg1[(size_t)row * HID + c]
                             : make_float4(0.f, 0.f, 0.f, 0.f);
        sA[r][c + 0] = fmaxf(v.x, 0.f);
        sA[r][c + 1] = fmaxf(v.y, 0.f);
        sA[r][c + 2] = fmaxf(v.z, 0.f);
        sA[r][c + 3] = fmaxf(v.w, 0.f);
    }
    __syncthreads();

    int m = tid & 31, g = tid >> 5;
    float acc[5] = {};
    #pragma unroll 8
    for (int k = 0; k < HID; k++) {
        float a = sA[m][k];
        #pragma unroll
        for (int j = 0; j < 5; j++)
            acc[j] = fmaf(a, sW[k * OUT_DIM + g * 5 + j], acc[j]);
    }
    int row = m0 + m;
    if (row < n) {
        #pragma unroll
        for (int j = 0; j < 5; j++)
            g_h2[(size_t)row * OUT_DIM + g * 5 + j] = acc[j];
    }
}

// ------------------------------------------------------- layer2 edge agg ----
__global__ void k_prefill2(const float* __restrict__ b2, float* __restrict__ out, int n) {
    int i = blockIdx.x * blockDim.x + threadIdx.x;  // over n*10 float4
    if (i < n * 10) {
        int c = i - (i / 10) * 10;
        ((float4*)out)[i] = ((const float4*)b2)[c];
    }
}

// thread per (edge, float4-chunk): 10 chunks cover 40 floats.
__global__ void k_edge2(const int* __restrict__ src, const int* __restrict__ dst,
                        float* __restrict__ out, int e) {
    int i = blockIdx.x * blockDim.x + threadIdx.x;
    if (i >= e * 10) return;
    int w = i / 10;
    int c = i - w * 10;
    int s = __ldg(&src[w]);
    int d = __ldg(&dst[w]);
    float co = g_coeff[w];
    float4 v = ((const float4*)g_h2)[(size_t)s * 10 + c];
    v.x *= co; v.y *= co; v.z *= co; v.w *= co;
    float* p = (float*)(((float4*)out) + ((size_t)d * 10 + c));
    asm volatile("red.global.add.v4.f32 [%0], {%1,%2,%3,%4};"
                 :: "l"(p), "f"(v.x), "f"(v.y), "f"(v.z), "f"(v.w) : "memory");
}

// ---------------------------------------------------------------- launch ----
extern "C" void kernel_launch(void* const* d_in, const int* in_sizes, int n_in,
                              void* d_out, int out_size) {
    const float* x   = (const float*)d_in[0];
    const int*   src = (const int*)d_in[1];
    const int*   dst = (const int*)d_in[2];
    const float* W1  = (const float*)d_in[3];
    const float* b1  = (const float*)d_in[4];
    const float* W2  = (const float*)d_in[5];
    const float* b2  = (const float*)d_in[6];
    float* out = (float*)d_out;

    int n = in_sizes[0] / IN_DIM;
    int e = in_sizes[1];

    k_zero_deg<<<(n + 255) / 256, 256>>>(n);
    k_count<<<(e + 255) / 256, 256>>>(dst, e);
    k_isd<<<(n + 255) / 256, 256>>>(n);
    k_coeff<<<(e + 255) / 256, 256>>>(src, dst, e);

    k_gemm1<<<(n + 63) / 64, 256>>>(x, W1, n);
    k_prefill1<<<(n * 32 + 255) / 256, 256>>>(b1, n);
    k_edge1<<<((e * 32) + 255) / 256, 256>>>(src, dst, e);

    k_gemm2<<<(n + 31) / 32, 256>>>(W2, n);
    k_prefill2<<<(n * 10 + 255) / 256, 256>>>(b2, out, n);
    k_edge2<<<((e * 10) + 255) / 256, 256>>>(src, dst, out, e);
}